// round 4
// baseline (speedup 1.0000x reference)
#include <cuda_runtime.h>
#include <cuda_bf16.h>

#define OUTSZ 224
#define NBINS 8
#define FW 512
#define FH 512
#define TPB 224                    // one thread per output column
#define SPLIT 8                    // CTAs per box
#define ROWS_PART (OUTSZ / SPLIT)  // 28 rows per CTA  (<=255 so 8-bit packed counts OK)
#define NBOX 512

// partial results: [box*SPLIT + part][bin]
__device__ float g_psum[NBOX * SPLIT * NBINS];
__device__ float g_pcnt[NBOX * SPLIT * NBINS];
__device__ unsigned int g_ticket[NBOX];   // zero-initialized; self-resetting

__global__ __launch_bounds__(TPB)
void vel_hist_kernel(const float* __restrict__ flows,
                     const float* __restrict__ boxes,
                     float* __restrict__ out)
{
    __shared__ float4 s_col[OUTSZ];        // per-column: {x0, x1, fx, mask}
    __shared__ float4 s_row[ROWS_PART];    // per-row:    {y0*FW, y1*FW, fy, mask}
    __shared__ float hsum[NBINS * 256];    // stride 256 for shift addressing
    __shared__ float hcnt[NBINS * 256];
    __shared__ unsigned int s_last;

    const int bx   = blockIdx.x;
    const int box  = bx >> 3;              // SPLIT = 8
    const int part = bx & 7;
    const int tid  = threadIdx.x;

    const float bf  = __ldg(boxes + box * 5 + 0);
    const float bx1 = __ldg(boxes + box * 5 + 1);
    const float by1 = __ldg(boxes + box * 5 + 2);
    const float bx2 = __ldg(boxes + box * 5 + 3);
    const float by2 = __ldg(boxes + box * 5 + 4);
    const int bidx = (int)bf;
    const float roi_w = fmaxf(bx2 - bx1, 1.0f);
    const float roi_h = fmaxf(by2 - by1, 1.0f);

    {   // x axis: all 224 threads, one column each
        float g = ((float)tid + 0.5f) * (1.0f / OUTSZ);
        float px = bx1 + g * roi_w;
        float mx = (px >= -1.0f && px <= (float)FW) ? 1.0f : 0.0f;
        float pcx = fminf(fmaxf(px, 0.0f), (float)(FW - 1));
        int xl = (int)floorf(pcx);
        int xh = min(xl + 1, FW - 1);
        s_col[tid] = make_float4(__int_as_float(xl), __int_as_float(xh),
                                 pcx - (float)xl, mx);
    }
    if (tid < ROWS_PART) {   // y axis: only this part's 28 rows
        int row = part * ROWS_PART + tid;
        float g = ((float)row + 0.5f) * (1.0f / OUTSZ);
        float py = by1 + g * roi_h;
        float my = (py >= -1.0f && py <= (float)FH) ? 1.0f : 0.0f;
        float pcy = fminf(fmaxf(py, 0.0f), (float)(FH - 1));
        int yl = (int)floorf(pcy);
        int yh = min(yl + 1, FH - 1);
        s_row[tid] = make_float4(__int_as_float(yl * FW), __int_as_float(yh * FW),
                                 pcy - (float)yl, my);
    }
#pragma unroll
    for (int b = 0; b < NBINS; b++)
        hsum[(b << 8) + tid] = 0.0f;
    __syncthreads();

    const float* __restrict__ c0 = flows + (size_t)bidx * 2u * FH * FW;
    const float* __restrict__ c1 = c0 + FH * FW;
    float* msum = hsum + tid;

    // column params: fixed per thread for the whole loop
    const float4 cp = s_col[tid];
    const int   xa = __float_as_int(cp.x), xb = __float_as_int(cp.y);
    const float fx = cp.z, gx = 1.0f - cp.z;
    const bool  vx = (cp.w != 0.0f);

    unsigned int cnt0 = 0u, cnt1 = 0u;   // 8 packed 8-bit counters

#pragma unroll 2
    for (int r = 0; r < ROWS_PART; r++) {
        float4 rp = s_row[r];            // uniform broadcast
        int r0 = __float_as_int(rp.x), r1 = __float_as_int(rp.y);
        float fy = rp.z, gy = 1.0f - rp.z;

        float w00 = gy * gx, w01 = gy * fx, w10 = fy * gx, w11 = fy * fx;
        int o00 = r0 + xa, o01 = r0 + xb, o10 = r1 + xa, o11 = r1 + xb;

        float a = w00 * __ldg(c0 + o00) + w01 * __ldg(c0 + o01)
                + w10 * __ldg(c0 + o10) + w11 * __ldg(c0 + o11);
        float b = w00 * __ldg(c1 + o00) + w01 * __ldg(c1 + o01)
                + w10 * __ldg(c1 + o10) + w11 * __ldg(c1 + o11);

        // masked samples -> exactly +0.0f (select, not multiply: 0*-x = -0
        // and atan2(-0, b<0) = -pi would bin as 0 instead of reference's 4)
        bool valid = vx && (rp.w != 0.0f);
        a = valid ? a : 0.0f;
        b = valid ? b : 0.0f;

        float r2 = fmaf(a, a, b * b);
        float mag = (r2 > 0.0f) ? r2 * rsqrtf(r2) : 0.0f;

        // bin = floor((atan2(a,b)+pi) * 8/(2*pi)) clipped -> octant of (b,a)
        int bin;
        if (a > 0.0f) {
            if (b > 0.0f)      bin = (a < b)   ? 4 : 5;
            else if (b < 0.0f) bin = (a > -b)  ? 6 : 7;
            else               bin = 6;
        } else if (a < 0.0f) {
            if (b > 0.0f)      bin = (-a <= b) ? 3 : 2;
            else if (b < 0.0f) bin = (a > b)   ? 0 : 1;
            else               bin = 2;
        } else {
            bin = (b < 0.0f) ? 7 : 4;
        }

        msum[bin << 8] += mag;
        unsigned int inc = 1u << ((bin & 3) << 3);
        if (bin & 4) cnt1 += inc; else cnt0 += inc;
    }

#pragma unroll
    for (int b = 0; b < 4; b++) {
        hcnt[((b    ) << 8) + tid] = (float)((cnt0 >> (b << 3)) & 0xFFu);
        hcnt[((b + 4) << 8) + tid] = (float)((cnt1 >> (b << 3)) & 0xFFu);
    }
    __syncthreads();

    // 7 warps reduce 8 bins (warp w -> bins w, w+7)
    int wid = tid >> 5, lane = tid & 31;
    for (int bin = wid; bin < NBINS; bin += 7) {
        float s = 0.0f, c = 0.0f;
#pragma unroll
        for (int t = 0; t < TPB; t += 32) {
            s += hsum[(bin << 8) + lane + t];
            c += hcnt[(bin << 8) + lane + t];
        }
#pragma unroll
        for (int d = 16; d > 0; d >>= 1) {
            s += __shfl_down_sync(0xffffffffu, s, d);
            c += __shfl_down_sync(0xffffffffu, c, d);
        }
        if (lane == 0) {
            g_psum[bx * NBINS + bin] = s;
            g_pcnt[bx * NBINS + bin] = c;
        }
    }

    // last-arriving CTA of each box finalizes (deterministic: fixed sum order)
    __threadfence();
    __syncthreads();
    if (tid == 0)
        s_last = (atomicAdd(&g_ticket[box], 1u) == SPLIT - 1) ? 1u : 0u;
    __syncthreads();
    if (s_last) {
        if (tid < NBINS) {
            float s = 0.0f, c = 0.0f;
#pragma unroll
            for (int p = 0; p < SPLIT; p++) {
                s += __ldcg(&g_psum[(box * SPLIT + p) * NBINS + tid]);
                c += __ldcg(&g_pcnt[(box * SPLIT + p) * NBINS + tid]);
            }
            out[box * NBINS + tid] = (c != 0.0f) ? (s / c) : 0.0f;
        }
        if (tid == 0) g_ticket[box] = 0u;   // reset for next replay
    }
}

extern "C" void kernel_launch(void* const* d_in, const int* in_sizes, int n_in,
                              void* d_out, int out_size) {
    const float* flows = (const float*)d_in[0];   // (8, 2, 512, 512) f32
    const float* boxes = (const float*)d_in[1];   // (512, 5) f32
    float* out = (float*)d_out;                   // (512, 8) f32
    int M = in_sizes[1] / 5;                      // 512
    vel_hist_kernel<<<M * SPLIT, TPB>>>(flows, boxes, out);
}

// round 7
// speedup vs baseline: 1.7121x; 1.7121x over previous
#include <cuda_runtime.h>
#include <cuda_bf16.h>

#define OUTSZ 224
#define NBINS 8
#define FW 512
#define FH 512
#define TPB 224                    // one thread per output column
#define SPLIT 8                    // CTAs per box
#define ROWS_PART (OUTSZ / SPLIT)  // 28 rows per CTA (counts <= 28 -> 8-bit fields OK)
#define NBOX 512

// partial results: [box*SPLIT + part][bin]
__device__ float g_psum[NBOX * SPLIT * NBINS];
__device__ float g_pcnt[NBOX * SPLIT * NBINS];

__global__ __launch_bounds__(TPB)
void vel_hist_part_kernel(const float* __restrict__ flows,
                          const float* __restrict__ boxes)
{
    __shared__ float4 s_col[OUTSZ];        // per-column: {x0, x1, fx, mask}
    __shared__ float4 s_row[ROWS_PART];    // per-row:    {y0*FW, y1*FW, fy, mask}
    __shared__ float hsum[NBINS * 256];
    __shared__ float hcnt[NBINS * 256];

    const int bx   = blockIdx.x;
    const int box  = bx >> 3;              // SPLIT = 8
    const int part = bx & 7;
    const int tid  = threadIdx.x;

    const float bf  = __ldg(boxes + box * 5 + 0);
    const float bx1 = __ldg(boxes + box * 5 + 1);
    const float by1 = __ldg(boxes + box * 5 + 2);
    const float bx2 = __ldg(boxes + box * 5 + 3);
    const float by2 = __ldg(boxes + box * 5 + 4);
    const int bidx = (int)bf;
    const float roi_w = fmaxf(bx2 - bx1, 1.0f);
    const float roi_h = fmaxf(by2 - by1, 1.0f);

    {   // x axis: one column per thread
        float g = ((float)tid + 0.5f) * (1.0f / OUTSZ);
        float px = bx1 + g * roi_w;
        float mx = (px >= -1.0f && px <= (float)FW) ? 1.0f : 0.0f;
        float pcx = fminf(fmaxf(px, 0.0f), (float)(FW - 1));
        int xl = (int)floorf(pcx);
        int xh = min(xl + 1, FW - 1);
        s_col[tid] = make_float4(__int_as_float(xl), __int_as_float(xh),
                                 pcx - (float)xl, mx);
    }
    if (tid < ROWS_PART) {   // y axis: this part's rows only
        int row = part * ROWS_PART + tid;
        float g = ((float)row + 0.5f) * (1.0f / OUTSZ);
        float py = by1 + g * roi_h;
        float my = (py >= -1.0f && py <= (float)FH) ? 1.0f : 0.0f;
        float pcy = fminf(fmaxf(py, 0.0f), (float)(FH - 1));
        int yl = (int)floorf(pcy);
        int yh = min(yl + 1, FH - 1);
        s_row[tid] = make_float4(__int_as_float(yl * FW), __int_as_float(yh * FW),
                                 pcy - (float)yl, my);
    }
#pragma unroll
    for (int b = 0; b < NBINS; b++)
        hsum[(b << 8) + tid] = 0.0f;
    __syncthreads();

    const float* __restrict__ c0 = flows + (size_t)bidx * 2u * FH * FW;
    const float* __restrict__ c1 = c0 + FH * FW;
    float* msum = hsum + tid;

    // per-thread column params (fixed for whole loop)
    const float4 cp = s_col[tid];
    const int   xa = __float_as_int(cp.x), xb = __float_as_int(cp.y);
    const float fx = cp.z;
    const bool  vx = (cp.w != 0.0f);

    unsigned int cnt0 = 0u, cnt1 = 0u;   // 8 packed 8-bit counters

    // row-cached x-lerped texel values. y advances by <=1 flow row per output
    // row and (y0,y1) is UNIFORM across the CTA, so reuse/shift decisions are
    // warp-uniform: no divergence, LDG count drops ~8x -> ~2.3 per sample.
    float t0 = 0.f, t1 = 0.f;      // top row, channels 0/1 (x-lerped)
    float bo0 = 0.f, bo1 = 0.f;    // bottom row
    float d0 = 0.f, d1 = 0.f;      // bottom - top
    int pr0 = -1, pr1 = -1;

    for (int r = 0; r < ROWS_PART; r++) {
        float4 rp = s_row[r];
        int r0 = __float_as_int(rp.x), r1 = __float_as_int(rp.y);
        float fy = rp.z;

        if (r0 != pr0) {                       // CTA-uniform branch
            if (r0 == pr1) {                   // slide down by one flow row
                t0 = bo0; t1 = bo1;
            } else {                           // cold / jump: load top row
                float la = __ldg(c0 + r0 + xa), lb = __ldg(c0 + r0 + xb);
                t0 = la + fx * (lb - la);
                la = __ldg(c1 + r0 + xa); lb = __ldg(c1 + r0 + xb);
                t1 = la + fx * (lb - la);
            }
            // load new bottom row
            {
                float la = __ldg(c0 + r1 + xa), lb = __ldg(c0 + r1 + xb);
                bo0 = la + fx * (lb - la);
                la = __ldg(c1 + r1 + xa); lb = __ldg(c1 + r1 + xb);
                bo1 = la + fx * (lb - la);
            }
            d0 = bo0 - t0; d1 = bo1 - t1;
            pr0 = r0; pr1 = r1;
        }

        float a = fmaf(fy, d0, t0);
        float b = fmaf(fy, d1, t1);

        // masked samples -> exactly +0.0f (select, not multiply: 0*-x = -0 and
        // atan2(-0, b<0) = -pi would bin as 0 instead of reference's 4)
        bool valid = vx && (rp.w != 0.0f);
        a = valid ? a : 0.0f;
        b = valid ? b : 0.0f;

        float r2 = fmaf(a, a, b * b);
        float mag = (r2 > 0.0f) ? r2 * rsqrtf(r2) : 0.0f;

        // bin = floor((atan2(a,b)+pi) * 8/(2*pi)) clipped -> octant of (b,a)
        int bin;
        if (a > 0.0f) {
            if (b > 0.0f)      bin = (a < b)   ? 4 : 5;
            else if (b < 0.0f) bin = (a > -b)  ? 6 : 7;
            else               bin = 6;
        } else if (a < 0.0f) {
            if (b > 0.0f)      bin = (-a <= b) ? 3 : 2;
            else if (b < 0.0f) bin = (a > b)   ? 0 : 1;
            else               bin = 2;
        } else {
            bin = (b < 0.0f) ? 7 : 4;
        }

        msum[bin << 8] += mag;
        unsigned int inc = 1u << ((bin & 3) << 3);
        if (bin & 4) cnt1 += inc; else cnt0 += inc;
    }

#pragma unroll
    for (int b = 0; b < 4; b++) {
        hcnt[((b    ) << 8) + tid] = (float)((cnt0 >> (b << 3)) & 0xFFu);
        hcnt[((b + 4) << 8) + tid] = (float)((cnt1 >> (b << 3)) & 0xFFu);
    }
    __syncthreads();

    // 7 warps reduce 8 bins (warp w -> bins w, w+7)
    int wid = tid >> 5, lane = tid & 31;
    for (int bin = wid; bin < NBINS; bin += 7) {
        float s = 0.0f, c = 0.0f;
#pragma unroll
        for (int t = 0; t < TPB; t += 32) {
            s += hsum[(bin << 8) + lane + t];
            c += hcnt[(bin << 8) + lane + t];
        }
#pragma unroll
        for (int d = 16; d > 0; d >>= 1) {
            s += __shfl_down_sync(0xffffffffu, s, d);
            c += __shfl_down_sync(0xffffffffu, c, d);
        }
        if (lane == 0) {
            g_psum[bx * NBINS + bin] = s;
            g_pcnt[bx * NBINS + bin] = c;
        }
    }
}

__global__ void vel_hist_finalize_kernel(float* __restrict__ out)
{
    int idx = blockIdx.x * blockDim.x + threadIdx.x;   // box*8 + bin
    if (idx >= NBOX * NBINS) return;
    int box = idx >> 3;
    int bin = idx & 7;
    float s = 0.0f, c = 0.0f;
#pragma unroll
    for (int p = 0; p < SPLIT; p++) {
        s += g_psum[(box * SPLIT + p) * NBINS + bin];
        c += g_pcnt[(box * SPLIT + p) * NBINS + bin];
    }
    out[idx] = (c != 0.0f) ? (s / c) : 0.0f;
}

extern "C" void kernel_launch(void* const* d_in, const int* in_sizes, int n_in,
                              void* d_out, int out_size) {
    const float* flows = (const float*)d_in[0];   // (8, 2, 512, 512) f32
    const float* boxes = (const float*)d_in[1];   // (512, 5) f32
    float* out = (float*)d_out;                   // (512, 8) f32
    vel_hist_part_kernel<<<NBOX * SPLIT, TPB>>>(flows, boxes);
    vel_hist_finalize_kernel<<<(NBOX * NBINS + 255) / 256, 256>>>(out);
}

// round 10
// speedup vs baseline: 1.7460x; 1.0198x over previous
#include <cuda_runtime.h>
#include <cuda_bf16.h>

#define OUTSZ 224
#define NBINS 8
#define FW 512
#define FH 512
#define TPB 224                     // one thread per output column
#define SPLIT 16                    // CTAs per box
#define ROWS_PART (OUTSZ / SPLIT)   // 14 output rows per CTA
#define NROWMAX 16                  // flow rows touched per part <= 15 (13-px span + 2)
#define NBOX 512

// partial results: [box*SPLIT + part][bin]
__device__ float g_psum[NBOX * SPLIT * NBINS];
__device__ float g_pcnt[NBOX * SPLIT * NBINS];

__global__ __launch_bounds__(TPB)
void vel_hist_part_kernel(const float* __restrict__ flows,
                          const float* __restrict__ boxes)
{
    __shared__ float2 s_lerp[NROWMAX * TPB];   // x-lerped (ch0, ch1) per flow row per column
    __shared__ float4 s_col[OUTSZ];            // {x0, x1, fx, mask}
    __shared__ float4 s_row[ROWS_PART];        // raw: {y0, y1, fy, mask} -> rewritten {idx0, idx1, fy, mask}
    __shared__ float  hsum[NBINS * 256];
    __shared__ unsigned int s_c0[256], s_c1[256];

    const int bx   = blockIdx.x;
    const int box  = bx >> 4;                  // SPLIT = 16
    const int part = bx & 15;
    const int tid  = threadIdx.x;

    const float bf  = __ldg(boxes + box * 5 + 0);
    const float bx1 = __ldg(boxes + box * 5 + 1);
    const float by1 = __ldg(boxes + box * 5 + 2);
    const float bx2 = __ldg(boxes + box * 5 + 3);
    const float by2 = __ldg(boxes + box * 5 + 4);
    const int bidx = (int)bf;
    const float roi_w = fmaxf(bx2 - bx1, 1.0f);
    const float roi_h = fmaxf(by2 - by1, 1.0f);

    {   // x axis: one column per thread
        float g = ((float)tid + 0.5f) * (1.0f / OUTSZ);
        float px = bx1 + g * roi_w;
        float mx = (px >= -1.0f && px <= (float)FW) ? 1.0f : 0.0f;
        float pcx = fminf(fmaxf(px, 0.0f), (float)(FW - 1));
        int xl = (int)floorf(pcx);
        int xh = min(xl + 1, FW - 1);
        s_col[tid] = make_float4(__int_as_float(xl), __int_as_float(xh),
                                 pcx - (float)xl, mx);
    }
    if (tid < ROWS_PART) {   // y axis: this part's rows (raw flow-row indices)
        int row = part * ROWS_PART + tid;
        float g = ((float)row + 0.5f) * (1.0f / OUTSZ);
        float py = by1 + g * roi_h;
        float my = (py >= -1.0f && py <= (float)FH) ? 1.0f : 0.0f;
        float pcy = fminf(fmaxf(py, 0.0f), (float)(FH - 1));
        int yl = (int)floorf(pcy);
        int yh = min(yl + 1, FH - 1);
        s_row[tid] = make_float4(__int_as_float(yl), __int_as_float(yh),
                                 pcy - (float)yl, my);
    }
#pragma unroll
    for (int b = 0; b < NBINS; b++)
        hsum[(b << 8) + tid] = 0.0f;
    __syncthreads();

    // rows are monotonic: needed flow rows = [ylo, yhi], contiguous, <= NROWMAX
    const int ylo = __float_as_int(s_row[0].x);
    int yhi = __float_as_int(s_row[ROWS_PART - 1].y);
    yhi = min(yhi, ylo + NROWMAX - 1);         // provable no-op; memory safety
    __syncthreads();                            // all raw reads done before rewrite

    if (tid < ROWS_PART) {                      // rewrite to smem row indices
        float4 rp = s_row[tid];
        int i0 = (__float_as_int(rp.x) - ylo) * TPB;
        int i1 = (__float_as_int(rp.y) - ylo) * TPB;
        s_row[tid] = make_float4(__int_as_float(i0), __int_as_float(i1), rp.z, rp.w);
    }

    // ---- Phase 1: branch-free bulk load, all LDGs independent (MLP-bound) ----
    const float4 cp = s_col[tid];
    const int   xa = __float_as_int(cp.x), xb = __float_as_int(cp.y);
    const float fx = cp.z;
    const bool  vx = (cp.w != 0.0f);

    const float* __restrict__ c0 = flows + (size_t)bidx * 2u * FH * FW;
    const float* __restrict__ c1 = c0 + FH * FW;

#pragma unroll 4
    for (int y = ylo; y <= yhi; y++) {
        int o = y * FW;
        float la = __ldg(c0 + o + xa), lb = __ldg(c0 + o + xb);
        float lc = __ldg(c1 + o + xa), ld = __ldg(c1 + o + xb);
        s_lerp[(y - ylo) * TPB + tid] =
            make_float2(la + fx * (lb - la), lc + fx * (ld - lc));
    }
    __syncthreads();

    // ---- Phase 2: branch-free compute from smem, fully unrolled ----
    float* msum = hsum + tid;
    unsigned int cnt0 = 0u, cnt1 = 0u;   // 8 packed 8-bit counters (max 14/bin)

#pragma unroll
    for (int r = 0; r < ROWS_PART; r++) {
        float4 rp = s_row[r];                        // uniform broadcast
        int i0 = __float_as_int(rp.x) + tid;
        int i1 = __float_as_int(rp.y) + tid;
        float fy = rp.z;
        float2 v0 = s_lerp[i0];
        float2 v1 = s_lerp[i1];

        float a = fmaf(fy, v1.x - v0.x, v0.x);
        float b = fmaf(fy, v1.y - v0.y, v0.y);

        // masked samples -> exactly +0.0f (select, not multiply: 0*-x = -0 and
        // atan2(-0, b<0) = -pi would bin as 0 instead of reference's 4)
        bool valid = vx && (rp.w != 0.0f);
        a = valid ? a : 0.0f;
        b = valid ? b : 0.0f;

        float r2 = fmaf(a, a, b * b);
        float mag = (r2 > 0.0f) ? r2 * rsqrtf(r2) : 0.0f;

        // bin = floor((atan2(a,b)+pi) * 8/(2*pi)) clipped -> octant of (b,a)
        int bin;
        if (a > 0.0f) {
            if (b > 0.0f)      bin = (a < b)   ? 4 : 5;
            else if (b < 0.0f) bin = (a > -b)  ? 6 : 7;
            else               bin = 6;
        } else if (a < 0.0f) {
            if (b > 0.0f)      bin = (-a <= b) ? 3 : 2;
            else if (b < 0.0f) bin = (a > b)   ? 0 : 1;
            else               bin = 2;
        } else {
            bin = (b < 0.0f) ? 7 : 4;
        }

        msum[bin << 8] += mag;
        unsigned int inc = 1u << ((bin & 3) << 3);
        if (bin & 4) cnt1 += inc; else cnt0 += inc;
    }

    s_c0[tid] = cnt0;
    s_c1[tid] = cnt1;
    __syncthreads();

    // 7 warps reduce 8 bins (warp w -> bins w, w+7)
    int wid = tid >> 5, lane = tid & 31;
    for (int bin = wid; bin < NBINS; bin += 7) {
        int sh = (bin & 3) << 3;
        const unsigned int* cc = (bin & 4) ? s_c1 : s_c0;
        float s = 0.0f;
        int   c = 0;
#pragma unroll
        for (int t = 0; t < TPB; t += 32) {
            s += hsum[(bin << 8) + lane + t];
            c += (int)((cc[lane + t] >> sh) & 0xFFu);
        }
#pragma unroll
        for (int d = 16; d > 0; d >>= 1) {
            s += __shfl_down_sync(0xffffffffu, s, d);
            c += __shfl_down_sync(0xffffffffu, c, d);
        }
        if (lane == 0) {
            g_psum[bx * NBINS + bin] = s;
            g_pcnt[bx * NBINS + bin] = (float)c;
        }
    }
}

__global__ void vel_hist_finalize_kernel(float* __restrict__ out)
{
    int idx = blockIdx.x * blockDim.x + threadIdx.x;   // box*8 + bin
    if (idx >= NBOX * NBINS) return;
    int box = idx >> 3;
    int bin = idx & 7;
    float s = 0.0f, c = 0.0f;
#pragma unroll
    for (int p = 0; p < SPLIT; p++) {
        s += g_psum[(box * SPLIT + p) * NBINS + bin];
        c += g_pcnt[(box * SPLIT + p) * NBINS + bin];
    }
    out[idx] = (c != 0.0f) ? (s / c) : 0.0f;
}

extern "C" void kernel_launch(void* const* d_in, const int* in_sizes, int n_in,
                              void* d_out, int out_size) {
    const float* flows = (const float*)d_in[0];   // (8, 2, 512, 512) f32
    const float* boxes = (const float*)d_in[1];   // (512, 5) f32
    float* out = (float*)d_out;                   // (512, 8) f32
    vel_hist_part_kernel<<<NBOX * SPLIT, TPB>>>(flows, boxes);
    vel_hist_finalize_kernel<<<(NBOX * NBINS + 255) / 256, 256>>>(out);
}

// round 12
// speedup vs baseline: 1.7905x; 1.0255x over previous
#include <cuda_runtime.h>
#include <cuda_bf16.h>

#define OUTSZ 224
#define NBINS 8
#define FW 512
#define FH 512
#define TPB 224                     // one thread per output column
#define SPLIT 16                    // CTAs per box
#define ROWS_PART (OUTSZ / SPLIT)   // 14 output rows per CTA
#define NROWMAX 15                  // flow rows per part: y-span <= 13 px -> <= 15 rows
#define NBOX 512

// partial results: [box*SPLIT + part][bin]
__device__ float g_psum[NBOX * SPLIT * NBINS];
__device__ float g_pcnt[NBOX * SPLIT * NBINS];
__device__ unsigned int g_ticket[NBOX];   // zero-init; self-resetting each replay

__global__ __launch_bounds__(TPB)
void vel_hist_kernel(const float* __restrict__ flows,
                     const float* __restrict__ boxes,
                     float* __restrict__ out)
{
    // s_lerp (phase 1/2) and the count-staging buffers (post-phase-2) are
    // disjoint in time -> alias them to save 2KB and reach 6 CTAs/SM.
    __shared__ __align__(16) char s_u[NROWMAX * TPB * sizeof(float2)];  // 26880 B
    float2*       s_lerp = (float2*)s_u;
    unsigned int* s_c0   = (unsigned int*)s_u;          // [224]
    unsigned int* s_c1   = ((unsigned int*)s_u) + TPB;  // [224]

    __shared__ float4 s_col[OUTSZ];          // {x0, x1, fx, mask}
    __shared__ float4 s_row[ROWS_PART];      // {y0,y1,fy,mask} -> {idx0,idx1,fy,mask}
    __shared__ float  hsum[NBINS * TPB];     // stride 224: 224%32==0 -> conflict-free
    __shared__ unsigned int s_flag;

    const int bx   = blockIdx.x;
    const int box  = bx >> 4;                // SPLIT = 16
    const int part = bx & 15;
    const int tid  = threadIdx.x;

    const float bf  = __ldg(boxes + box * 5 + 0);
    const float bx1 = __ldg(boxes + box * 5 + 1);
    const float by1 = __ldg(boxes + box * 5 + 2);
    const float bx2 = __ldg(boxes + box * 5 + 3);
    const float by2 = __ldg(boxes + box * 5 + 4);
    const int bidx = (int)bf;
    const float roi_w = fmaxf(bx2 - bx1, 1.0f);
    const float roi_h = fmaxf(by2 - by1, 1.0f);

    {   // x axis: one column per thread
        float g = ((float)tid + 0.5f) * (1.0f / OUTSZ);
        float px = bx1 + g * roi_w;
        float mx = (px >= -1.0f && px <= (float)FW) ? 1.0f : 0.0f;
        float pcx = fminf(fmaxf(px, 0.0f), (float)(FW - 1));
        int xl = (int)floorf(pcx);
        int xh = min(xl + 1, FW - 1);
        s_col[tid] = make_float4(__int_as_float(xl), __int_as_float(xh),
                                 pcx - (float)xl, mx);
    }
    if (tid < ROWS_PART) {   // y axis: raw flow-row indices for this part
        int row = part * ROWS_PART + tid;
        float g = ((float)row + 0.5f) * (1.0f / OUTSZ);
        float py = by1 + g * roi_h;
        float my = (py >= -1.0f && py <= (float)FH) ? 1.0f : 0.0f;
        float pcy = fminf(fmaxf(py, 0.0f), (float)(FH - 1));
        int yl = (int)floorf(pcy);
        int yh = min(yl + 1, FH - 1);
        s_row[tid] = make_float4(__int_as_float(yl), __int_as_float(yh),
                                 pcy - (float)yl, my);
    }
#pragma unroll
    for (int b = 0; b < NBINS; b++)
        hsum[b * TPB + tid] = 0.0f;
    __syncthreads();

    // needed flow rows = [ylo, yhi], contiguous (rows monotone), <= NROWMAX
    const int ylo = __float_as_int(s_row[0].x);
    int yhi = __float_as_int(s_row[ROWS_PART - 1].y);
    yhi = min(yhi, ylo + NROWMAX - 1);       // provable no-op; memory safety
    __syncthreads();                          // raw reads done before rewrite

    if (tid < ROWS_PART) {                    // rewrite to s_lerp element offsets
        float4 rp = s_row[tid];
        int i0 = (__float_as_int(rp.x) - ylo) * TPB;
        int i1 = (__float_as_int(rp.y) - ylo) * TPB;
        s_row[tid] = make_float4(__int_as_float(i0), __int_as_float(i1), rp.z, rp.w);
    }

    // ---- Phase 1: branch-free bulk load, all LDGs independent (MLP-bound) ----
    const float4 cp = s_col[tid];
    const int   xa = __float_as_int(cp.x), xb = __float_as_int(cp.y);
    const float fx = cp.z;
    const bool  vx = (cp.w != 0.0f);

    const float* __restrict__ c0 = flows + (size_t)bidx * 2u * FH * FW;
    const float* __restrict__ c1 = c0 + FH * FW;

#pragma unroll 4
    for (int y = ylo; y <= yhi; y++) {
        int o = y * FW;
        float la = __ldg(c0 + o + xa), lb = __ldg(c0 + o + xb);
        float lc = __ldg(c1 + o + xa), ld = __ldg(c1 + o + xb);
        s_lerp[(y - ylo) * TPB + tid] =
            make_float2(la + fx * (lb - la), lc + fx * (ld - lc));
    }
    __syncthreads();

    // ---- Phase 2: branch-free compute from smem, fully unrolled ----
    float* msum = hsum + tid;
    unsigned int cnt0 = 0u, cnt1 = 0u;   // 8 packed 8-bit counters (max 14/bin)

#pragma unroll
    for (int r = 0; r < ROWS_PART; r++) {
        float4 rp = s_row[r];                 // uniform broadcast
        int i0 = __float_as_int(rp.x) + tid;
        int i1 = __float_as_int(rp.y) + tid;
        float fy = rp.z;
        float2 v0 = s_lerp[i0];
        float2 v1 = s_lerp[i1];

        float a = fmaf(fy, v1.x - v0.x, v0.x);
        float b = fmaf(fy, v1.y - v0.y, v0.y);

        // masked samples -> exactly +0.0f (select, not multiply: 0*-x = -0 and
        // atan2(-0, b<0) = -pi would bin as 0 instead of reference's 4)
        bool valid = vx && (rp.w != 0.0f);
        a = valid ? a : 0.0f;
        b = valid ? b : 0.0f;

        float r2 = fmaf(a, a, b * b);
        // r2==0 -> 0*inf = NaN -> fmaxf picks the non-NaN operand 0.0f
        float mag = fmaxf(r2 * rsqrtf(r2), 0.0f);

        // bin = floor((atan2(a,b)+pi) * 8/(2*pi)) clipped -> octant of (b,a)
        int bin;
        if (a > 0.0f) {
            if (b > 0.0f)      bin = (a < b)   ? 4 : 5;
            else if (b < 0.0f) bin = (a > -b)  ? 6 : 7;
            else               bin = 6;
        } else if (a < 0.0f) {
            if (b > 0.0f)      bin = (-a <= b) ? 3 : 2;
            else if (b < 0.0f) bin = (a > b)   ? 0 : 1;
            else               bin = 2;
        } else {
            bin = (b < 0.0f) ? 7 : 4;
        }

        msum[bin * TPB] += mag;
        unsigned int inc = 1u << ((bin & 3) << 3);
        if (bin & 4) cnt1 += inc; else cnt0 += inc;
    }

    __syncthreads();          // all s_lerp reads done before aliasing as s_c
    s_c0[tid] = cnt0;
    s_c1[tid] = cnt1;
    __syncthreads();

    // 7 warps reduce 8 bins (warp w -> bins w, w+7)
    int wid = tid >> 5, lane = tid & 31;
    for (int bin = wid; bin < NBINS; bin += 7) {
        int sh = (bin & 3) << 3;
        const unsigned int* cc = (bin & 4) ? s_c1 : s_c0;
        float s = 0.0f;
        int   c = 0;
#pragma unroll
        for (int t = 0; t < TPB; t += 32) {
            s += hsum[bin * TPB + lane + t];
            c += (int)((cc[lane + t] >> sh) & 0xFFu);
        }
#pragma unroll
        for (int d = 16; d > 0; d >>= 1) {
            s += __shfl_down_sync(0xffffffffu, s, d);
            c += __shfl_down_sync(0xffffffffu, c, d);
        }
        if (lane == 0) {
            g_psum[bx * NBINS + bin] = s;
            g_pcnt[bx * NBINS + bin] = (float)c;
        }
    }

    // ---- fused finalize: last-arriving CTA per box combines the partials ----
    // release-atomic from ONE thread (cumulative over the CTA via the barrier)
    // -> no __threadfence, no CCTL.IVALL L1 wipe (that was R4's regression).
    __syncthreads();
    if (tid == 0) {
        unsigned int old;
        asm volatile("atom.release.gpu.global.add.u32 %0, [%1], %2;"
                     : "=r"(old) : "l"(&g_ticket[box]), "r"(1u) : "memory");
        s_flag = (old == SPLIT - 1) ? 1u : 0u;
    }
    __syncthreads();
    if (s_flag) {
        if (tid < NBINS) {
            float s = 0.0f, c = 0.0f;
#pragma unroll
            for (int p = 0; p < SPLIT; p++) {   // __ldcg: L1-bypass, reads L2
                s += __ldcg(&g_psum[(box * SPLIT + p) * NBINS + tid]);
                c += __ldcg(&g_pcnt[(box * SPLIT + p) * NBINS + tid]);
            }
            out[box * NBINS + tid] = (c != 0.0f) ? (s / c) : 0.0f;
        }
        if (tid == 0) g_ticket[box] = 0u;   // reset for next graph replay
    }
}

extern "C" void kernel_launch(void* const* d_in, const int* in_sizes, int n_in,
                              void* d_out, int out_size) {
    const float* flows = (const float*)d_in[0];   // (8, 2, 512, 512) f32
    const float* boxes = (const float*)d_in[1];   // (512, 5) f32
    float* out = (float*)d_out;                   // (512, 8) f32
    vel_hist_kernel<<<NBOX * SPLIT, TPB>>>(flows, boxes, out);
}

// round 14
// speedup vs baseline: 2.1932x; 1.2249x over previous
#include <cuda_runtime.h>
#include <cuda_bf16.h>

#define OUTSZ 224
#define NBINS 8
#define FW 512
#define FH 512
#define TPB 224                     // one thread per output column
#define SPLIT 16                    // CTAs per box
#define ROWS_PART (OUTSZ / SPLIT)   // 14 output rows per CTA
#define NROWMAX 15                  // y-span <= 13 px over 14 rows -> <= 15 flow rows
#define ZROW NROWMAX                // extra zeroed row for masked rows
#define NBOX 512

// partial results: [box*SPLIT + part][bin]
__device__ float g_psum[NBOX * SPLIT * NBINS];
__device__ float g_pcnt[NBOX * SPLIT * NBINS];
__device__ unsigned int g_ticket[NBOX];   // zero-init; self-resetting each replay

__global__ __launch_bounds__(TPB)
void vel_hist_kernel(const float* __restrict__ flows,
                     const float* __restrict__ boxes,
                     float* __restrict__ out)
{
    // s_lerp (phases 1/2) aliased with count-staging buffers (post-loop)
    __shared__ __align__(16) char s_u[(NROWMAX + 1) * TPB * sizeof(float2)]; // 28672 B
    float2*       s_lerp = (float2*)s_u;
    unsigned int* s_c0   = (unsigned int*)s_u;
    unsigned int* s_c1   = ((unsigned int*)s_u) + TPB;

    __shared__ float4 s_row[ROWS_PART];   // {i0_bytes, i1_bytes, fy, -}
    __shared__ float  hsum[NBINS * TPB];  // stride 224: conflict-free
    __shared__ unsigned int s_flag;

    const int bx   = blockIdx.x;
    const int box  = bx >> 4;             // SPLIT = 16
    const int part = bx & 15;
    const int tid  = threadIdx.x;

    const float bf  = __ldg(boxes + box * 5 + 0);
    const float bx1 = __ldg(boxes + box * 5 + 1);
    const float by1 = __ldg(boxes + box * 5 + 2);
    const float bx2 = __ldg(boxes + box * 5 + 3);
    const float by2 = __ldg(boxes + box * 5 + 4);
    const int bidx = (int)bf;
    const float roi_w = fmaxf(bx2 - bx1, 1.0f);
    const float roi_h = fmaxf(by2 - by1, 1.0f);

    // ---- per-thread column params (no smem) ----
    float fx; int xa, xb; bool vx;
    {
        float g = ((float)tid + 0.5f) * (1.0f / OUTSZ);
        float px = bx1 + g * roi_w;
        vx = (px >= -1.0f && px <= (float)FW);
        float pcx = fminf(fmaxf(px, 0.0f), (float)(FW - 1));
        xa = (int)floorf(pcx);
        xb = min(xa + 1, FW - 1);
        fx = pcx - (float)xa;
    }

    // ---- flow-row range for this part (identical computation in all threads) ----
    const int row0 = part * ROWS_PART;
    int ylo, yhi;
    {
        float g0 = ((float)row0 + 0.5f) * (1.0f / OUTSZ);
        float p0 = fminf(fmaxf(by1 + g0 * roi_h, 0.0f), (float)(FH - 1));
        ylo = (int)floorf(p0);
        float g1 = ((float)(row0 + ROWS_PART - 1) + 0.5f) * (1.0f / OUTSZ);
        float p1 = fminf(fmaxf(by1 + g1 * roi_h, 0.0f), (float)(FH - 1));
        yhi = min((int)floorf(p1) + 1, FH - 1);
        yhi = min(yhi, ylo + NROWMAX - 1);    // provable no-op; memory safety
    }

    if (tid < ROWS_PART) {   // y axis: byte offsets into s_lerp (mask folded in)
        int row = row0 + tid;
        float g = ((float)row + 0.5f) * (1.0f / OUTSZ);
        float py = by1 + g * roi_h;
        bool vy = (py >= -1.0f && py <= (float)FH);
        float pcy = fminf(fmaxf(py, 0.0f), (float)(FH - 1));
        int yl = (int)floorf(pcy);
        int yh = min(yl + 1, FH - 1);
        float fy = pcy - (float)yl;
        int i0b = (yl - ylo) * (TPB * 8);
        int i1b = (yh - ylo) * (TPB * 8);
        if (!vy) { i0b = ZROW * (TPB * 8); i1b = i0b; }   // -> zeroed row => (+0,+0)
        s_row[tid] = make_float4(__int_as_float(i0b), __int_as_float(i1b), fy, 0.0f);
    }
#pragma unroll
    for (int b = 0; b < NBINS; b++)
        hsum[b * TPB + tid] = 0.0f;

    // ---- Phase 1: branch-free bulk load, all LDGs independent (MLP-bound) ----
    const float* __restrict__ c0 = flows + (size_t)bidx * 2u * FH * FW;
    const float* __restrict__ c1 = c0 + FH * FW;

#pragma unroll 5
    for (int y = ylo; y <= yhi; y++) {
        int o = y * FW;
        float la = __ldg(c0 + o + xa), lb = __ldg(c0 + o + xb);
        float lc = __ldg(c1 + o + xa), ld = __ldg(c1 + o + xb);
        float w0 = la + fx * (lb - la);
        float w1 = lc + fx * (ld - lc);
        if (!vx) { w0 = 0.0f; w1 = 0.0f; }   // masked column => exact (+0,+0)
        s_lerp[(y - ylo) * TPB + tid] = make_float2(w0, w1);
    }
    s_lerp[ZROW * TPB + tid] = make_float2(0.0f, 0.0f);   // zero row for masked rows
    __syncthreads();

    // ---- Phase 2: branch-free compute, fully unrolled, lean ALU ----
    const char* lb_base = (const char*)s_lerp + tid * sizeof(float2);
    float* msum = hsum + tid;
    unsigned int cnt0 = 0u, cnt1 = 0u;   // bins 0-3 / 4-7, 8-bit fields (max 14)

#pragma unroll
    for (int r = 0; r < ROWS_PART; r++) {
        float4 rp = s_row[r];                 // uniform LDS.128
        float2 v0 = *(const float2*)(lb_base + __float_as_int(rp.x));
        float2 v1 = *(const float2*)(lb_base + __float_as_int(rp.y));
        float fy = rp.z;

        float a = fmaf(fy, v1.x - v0.x, v0.x);
        float b = fmaf(fy, v1.y - v0.y, v0.y);

        float r2 = fmaf(a, a, b * b);
        float mag = r2 * rsqrtf(r2 + 1e-38f);   // r2=0 -> 0*finite = +0, no NaN

        // octant bin via LUT: idx = (a<0)<<2 | (b<0)<<1 | (|a|<=|b|)
        // (<= makes (+-0,+-0) -> bin 4 exactly; FSETP: -0 == +0)
        bool pa = a < 0.0f;
        bool pb = b < 0.0f;
        bool pc = fabsf(a) <= fabsf(b);
        int sh = (pa ? 16 : 0) + (pb ? 8 : 0) + (pc ? 4 : 0);
        unsigned int t = 0x01327645u >> sh;
        int bin = t & 7;

        msum[bin * TPB] += mag;
        unsigned int inc = 1u << ((t & 3) << 3);   // bin&3 == t&3
        if (pa) cnt0 += inc; else cnt1 += inc;     // a<0 <=> bin in 0..3
    }

    __syncthreads();          // s_lerp reads done before aliasing as s_c
    s_c0[tid] = cnt0;
    s_c1[tid] = cnt1;
    __syncthreads();

    // 7 warps reduce 8 bins (warp w -> bins w, w+7)
    int wid = tid >> 5, lane = tid & 31;
    for (int bin = wid; bin < NBINS; bin += 7) {
        int shb = (bin & 3) << 3;
        const unsigned int* cc = (bin & 4) ? s_c1 : s_c0;
        float s = 0.0f;
        int   c = 0;
#pragma unroll
        for (int u = 0; u < TPB; u += 32) {
            s += hsum[bin * TPB + lane + u];
            c += (int)((cc[lane + u] >> shb) & 0xFFu);
        }
#pragma unroll
        for (int d = 16; d > 0; d >>= 1) {
            s += __shfl_down_sync(0xffffffffu, s, d);
            c += __shfl_down_sync(0xffffffffu, c, d);
        }
        if (lane == 0) {
            g_psum[bx * NBINS + bin] = s;
            g_pcnt[bx * NBINS + bin] = (float)c;
        }
    }

    // ---- fused finalize: last CTA per box combines partials ----
    // one release-atomic per CTA: ordering without __threadfence (no CCTL.IVALL)
    __syncthreads();
    if (tid == 0) {
        unsigned int old;
        asm volatile("atom.release.gpu.global.add.u32 %0, [%1], %2;"
                     : "=r"(old) : "l"(&g_ticket[box]), "r"(1u) : "memory");
        s_flag = (old == SPLIT - 1) ? 1u : 0u;
    }
    __syncthreads();
    if (s_flag) {
        if (tid < NBINS) {
            float s = 0.0f, c = 0.0f;
#pragma unroll
            for (int p = 0; p < SPLIT; p++) {   // __ldcg: L1-bypass, L2-coherent
                s += __ldcg(&g_psum[(box * SPLIT + p) * NBINS + tid]);
                c += __ldcg(&g_pcnt[(box * SPLIT + p) * NBINS + tid]);
            }
            out[box * NBINS + tid] = (c != 0.0f) ? (s / c) : 0.0f;
        }
        if (tid == 0) g_ticket[box] = 0u;   // reset for next graph replay
    }
}

extern "C" void kernel_launch(void* const* d_in, const int* in_sizes, int n_in,
                              void* d_out, int out_size) {
    const float* flows = (const float*)d_in[0];   // (8, 2, 512, 512) f32
    const float* boxes = (const float*)d_in[1];   // (512, 5) f32
    float* out = (float*)d_out;                   // (512, 8) f32
    vel_hist_kernel<<<NBOX * SPLIT, TPB>>>(flows, boxes, out);
}